// round 15
// baseline (speedup 1.0000x reference)
#include <cuda_runtime.h>
#include <cuda_fp16.h>
#include <cstdint>

// ============================================================================
// out[M,N] = X[M,K] @ sign(W)[N,K]^T + bias[N],  M=N=K=4096, fp32.
// sm_103 plain PTX target => legacy mma.sync fp16 path.
// History: fp16 single-pass 412 (R6); 2CTA/SM 356 (R7); 4-warp 64x64 340 (R8);
// persistent 334 (R13); load-before-wait + MLP4 converts 324 (R14 BEST;
// ncu: tensor 77.2%, DRAM 4%, L1 43% -> no BW limit, correlated stalls).
// R15: 8 warps (2Mx4N, warp 64x32) so each SMSP holds 2 warps per CTA ->
// a CTA barrier stalls only half the warps per SMSP; better HMMA coverage.
// L1 headroom absorbs the extra fragment traffic. All else = R14.
// ============================================================================

static constexpr int MM = 4096;
static constexpr int NN = 4096;
static constexpr int KK = 4096;

static constexpr int BM = 128;
static constexpr int BN = 128;
static constexpr int BK = 64;            // 64 fp16 = 128B row
static constexpr int STAGES = 3;
static constexpr int CPT = KK / BK;      // 64 chunks per tile
static constexpr int THREADS = 256;      // 8 warps: 2 (M) x 4 (N), warp 64x32
static constexpr int NTILES = (MM / BM) * (NN / BN);  // 1024

// SMEM stage layout (bytes)
static constexpr int A_BYTES = BM * 128;           // 16384
static constexpr int B_BYTES = BN * 128;           // 16384
static constexpr int A_OFF = 0;
static constexpr int B_OFF = A_BYTES;
static constexpr int STAGE_BYTES = A_BYTES + B_BYTES;   // 32768
static constexpr int SMEM_TOTAL = STAGES * STAGE_BYTES; // 98304

// ---------------------------------------------------------------------------
// Scratch (allocation-free)
// ---------------------------------------------------------------------------
__device__ __align__(1024) __half g_xa[(size_t)MM * KK];
__device__ __align__(1024) __half g_wb[(size_t)NN * KK];

// ---------------------------------------------------------------------------
// helpers
// ---------------------------------------------------------------------------
__device__ __forceinline__ uint32_t smem_u32(const void* p) {
    uint32_t a;
    asm("{ .reg .u64 t; cvta.to.shared.u64 t, %1; cvt.u32.u64 %0, t; }"
        : "=r"(a) : "l"(p));
    return a;
}

#define CP_ASYNC_16(dst, src) \
    asm volatile("cp.async.cg.shared.global [%0], [%1], 16;" \
        :: "r"(dst), "l"(src) : "memory")
#define CP_ASYNC_COMMIT() asm volatile("cp.async.commit_group;" ::: "memory")
#define CP_ASYNC_WAIT_2() asm volatile("cp.async.wait_group 2;" ::: "memory")

__device__ __forceinline__ void ldmatrix_x4(uint32_t& r0, uint32_t& r1,
                                            uint32_t& r2, uint32_t& r3,
                                            uint32_t addr) {
    asm volatile("ldmatrix.sync.aligned.m8n8.x4.shared.b16 {%0,%1,%2,%3}, [%4];"
                 : "=r"(r0), "=r"(r1), "=r"(r2), "=r"(r3) : "r"(addr));
}

__device__ __forceinline__ void mma_f16(float* d, const uint32_t* a,
                                        uint32_t b0, uint32_t b1) {
    asm volatile(
        "mma.sync.aligned.m16n8k16.row.col.f32.f16.f16.f32 "
        "{%0,%1,%2,%3}, {%4,%5,%6,%7}, {%8,%9}, {%0,%1,%2,%3};"
        : "+f"(d[0]), "+f"(d[1]), "+f"(d[2]), "+f"(d[3])
        : "r"(a[0]), "r"(a[1]), "r"(a[2]), "r"(a[3]), "r"(b0), "r"(b1));
}

// ---------------------------------------------------------------------------
// Fused conversion kernel, MLP=4 (unchanged from R14)
// ---------------------------------------------------------------------------
__global__ void __launch_bounds__(256) convert_fused_kernel(
    const float4* __restrict__ x, const float4* __restrict__ w,
    uint2* __restrict__ xa, uint2* __restrict__ wb, int nbx, int quarter) {
    const int b = blockIdx.x;
    if (b < nbx) {
        const int i = b * 256 + threadIdx.x;
        float4 v[4];
        #pragma unroll
        for (int k = 0; k < 4; k++) v[k] = x[i + k * quarter];
        #pragma unroll
        for (int k = 0; k < 4; k++) {
            __half2 p01 = __floats2half2_rn(v[k].x, v[k].y);
            __half2 p23 = __floats2half2_rn(v[k].z, v[k].w);
            uint2 p;
            p.x = *reinterpret_cast<uint32_t*>(&p01);
            p.y = *reinterpret_cast<uint32_t*>(&p23);
            xa[i + k * quarter] = p;
        }
    } else {
        const int i = (b - nbx) * 256 + threadIdx.x;
        float4 v[4];
        #pragma unroll
        for (int k = 0; k < 4; k++) v[k] = w[i + k * quarter];
        #pragma unroll
        for (int k = 0; k < 4; k++) {
            float s0 = (v[k].x > 0.f) ? 1.f : ((v[k].x < 0.f) ? -1.f : 0.f);
            float s1 = (v[k].y > 0.f) ? 1.f : ((v[k].y < 0.f) ? -1.f : 0.f);
            float s2 = (v[k].z > 0.f) ? 1.f : ((v[k].z < 0.f) ? -1.f : 0.f);
            float s3 = (v[k].w > 0.f) ? 1.f : ((v[k].w < 0.f) ? -1.f : 0.f);
            __half2 p01 = __floats2half2_rn(s0, s1);
            __half2 p23 = __floats2half2_rn(s2, s3);
            uint2 p;
            p.x = *reinterpret_cast<uint32_t*>(&p01);
            p.y = *reinterpret_cast<uint32_t*>(&p23);
            wb[i + k * quarter] = p;
        }
    }
}

// ---------------------------------------------------------------------------
// Persistent GEMM kernel (single fp16 pass, 8 warps, 2 CTAs/SM)
// ---------------------------------------------------------------------------
__global__ void __launch_bounds__(THREADS, 2)
bingemm_kernel(const __half* __restrict__ xa,
               const __half* __restrict__ wb,
               const float* __restrict__ bias,
               float* __restrict__ out) {
    extern __shared__ __align__(1024) char smem[];
    const uint32_t sb = smem_u32(smem);

    const int tid = threadIdx.x;
    const int wid = tid >> 5;
    const int lane = tid & 31;
    const int warp_m = wid & 1;    // 0..1 -> 64 rows
    const int warp_n = wid >> 1;   // 0..3 -> 32 cols
    const int G = gridDim.x;

    const int ntiles = (NTILES - 1 - (int)blockIdx.x) / G + 1;
    const int ntotal = ntiles * CPT;   // global chunk count

    // --- cp.async tile loader: 256 threads, row=128B=8x16B chunks, swizzle ---
    const int ld_row = tid >> 3;   // 0..31
    const int ld_chunk = tid & 7;  // 0..7

    auto load_gchunk = [&](int stage, int gc) {
        const int tile = blockIdx.x + (gc >> 6) * G;   // gc/CPT
        const int m0 = (tile >> 5) * BM;               // tile / 32
        const int n0 = (tile & 31) * BN;               // tile % 32
        const int k0 = (gc & 63) * BK;
        const uint32_t sbase = sb + stage * STAGE_BYTES;
        #pragma unroll
        for (int i = 0; i < 4; i++) {
            int row = i * 32 + ld_row;
            uint32_t soff = row * 128 + ((ld_chunk ^ (row & 7)) << 4);
            CP_ASYNC_16(sbase + A_OFF + soff,
                        xa + (size_t)(m0 + row) * KK + k0 + ld_chunk * 8);
        }
        #pragma unroll
        for (int i = 0; i < 4; i++) {
            int row = i * 32 + ld_row;
            uint32_t soff = row * 128 + ((ld_chunk ^ (row & 7)) << 4);
            CP_ASYNC_16(sbase + B_OFF + soff,
                        wb + (size_t)(n0 + row) * KK + k0 + ld_chunk * 8);
        }
    };

    // prologue: 2 stages in flight (once per CTA)
    load_gchunk(0, 0); CP_ASYNC_COMMIT();
    load_gchunk(1, 1); CP_ASYNC_COMMIT();

    // --- ldmatrix per-thread address components ---
    const int mt = lane >> 3;            // matrix index 0..3
    const int lrow = lane & 7;
    const int a_row = warp_m * 64 + lrow + ((mt & 1) << 3);   // + mi*16
    const int a_koff = mt >> 1;
    const int b_row = warp_n * 32 + lrow + ((mt >> 1) << 3);  // + nj2*16
    const int b_koff = mt & 1;

    float acc[4][4][4];                  // mi, nj (4 x n8), quad
    #pragma unroll
    for (int mi = 0; mi < 4; mi++)
        #pragma unroll
        for (int nj = 0; nj < 4; nj++)
            #pragma unroll
            for (int q = 0; q < 4; q++) acc[mi][nj][q] = 0.f;

    const int qcol = (lane & 3) * 2;

    for (int ti = 0; ti < ntiles; ti++) {
        for (int c = 0; c < CPT; c++) {
            const int gc = ti * CPT + c;
            // Issue chunk gc+2's loads BEFORE waiting (R14 win): stage
            // (gc+2)%3 held chunk gc-1, finished before last bottom sync.
            if (gc + 2 < ntotal) load_gchunk((gc + 2) % STAGES, gc + 2);
            CP_ASYNC_COMMIT();
            CP_ASYNC_WAIT_2();
            __syncthreads();

            const uint32_t sbase = sb + (gc % STAGES) * STAGE_BYTES;

            #pragma unroll
            for (int ks = 0; ks < 4; ks++) {
                // B fragments: 2 x ldmatrix.x4 -> 4 n8 slices (32 cols)
                uint32_t b[2][4];
                #pragma unroll
                for (int nj2 = 0; nj2 < 2; nj2++) {
                    int row = b_row + nj2 * 16;
                    int kch = ks * 2 + b_koff;
                    uint32_t off = row * 128 + ((kch ^ (row & 7)) << 4);
                    ldmatrix_x4(b[nj2][0], b[nj2][1], b[nj2][2], b[nj2][3],
                                sbase + B_OFF + off);
                }
                #pragma unroll
                for (int mi = 0; mi < 4; mi++) {
                    int row = a_row + mi * 16;
                    int kch = ks * 2 + a_koff;
                    uint32_t off = row * 128 + ((kch ^ (row & 7)) << 4);
                    uint32_t a[4];
                    ldmatrix_x4(a[0], a[1], a[2], a[3], sbase + A_OFF + off);
                    #pragma unroll
                    for (int nj2 = 0; nj2 < 2; nj2++) {
                        mma_f16(acc[mi][nj2 * 2 + 0], a, b[nj2][0], b[nj2][1]);
                        mma_f16(acc[mi][nj2 * 2 + 1], a, b[nj2][2], b[nj2][3]);
                    }
                }
            }
            __syncthreads();
        }

        // ---- epilogue for this tile (next tile's loads already in flight) ----
        {
            const int tile = blockIdx.x + ti * G;
            const int m0 = (tile >> 5) * BM;
            const int n0 = (tile & 31) * BN;

            #pragma unroll
            for (int mi = 0; mi < 4; mi++) {
                int r0 = m0 + warp_m * 64 + mi * 16 + (lane >> 2);
                float* p0 = out + (size_t)r0 * NN + n0 + warp_n * 32 + qcol;
                float* p1 = p0 + 8 * NN;
                #pragma unroll
                for (int nj = 0; nj < 4; nj++) {
                    float2 bv = *reinterpret_cast<const float2*>(
                        bias + n0 + warp_n * 32 + nj * 8 + qcol);
                    float2 v0, v1;
                    v0.x = acc[mi][nj][0] + bv.x;
                    v0.y = acc[mi][nj][1] + bv.y;
                    v1.x = acc[mi][nj][2] + bv.x;
                    v1.y = acc[mi][nj][3] + bv.y;
                    *reinterpret_cast<float2*>(p0 + nj * 8) = v0;
                    *reinterpret_cast<float2*>(p1 + nj * 8) = v1;
                    acc[mi][nj][0] = 0.f; acc[mi][nj][1] = 0.f;
                    acc[mi][nj][2] = 0.f; acc[mi][nj][3] = 0.f;
                }
            }
        }
    }
}

// ---------------------------------------------------------------------------
// Host launch
// ---------------------------------------------------------------------------
extern "C" void kernel_launch(void* const* d_in, const int* in_sizes, int n_in,
                              void* d_out, int out_size) {
    const float* x    = (const float*)d_in[0];
    const float* w    = (const float*)d_in[1];
    const float* bias = (const float*)d_in[2];
    float* out = (float*)d_out;

    void *p_xa = nullptr, *p_wb = nullptr;
    cudaGetSymbolAddress(&p_xa, g_xa);
    cudaGetSymbolAddress(&p_wb, g_wb);

    const int n4 = MM * KK / 4;          // float4 count per tensor
    const int quarter = n4 / 4;
    const int nbx = quarter / 256;       // blocks per tensor (each does 4x)
    convert_fused_kernel<<<2 * nbx, 256>>>((const float4*)x, (const float4*)w,
                                           (uint2*)p_xa, (uint2*)p_wb,
                                           nbx, quarter);

    static bool attr_set = false;
    if (!attr_set) {
        cudaFuncSetAttribute(bingemm_kernel,
                             cudaFuncAttributeMaxDynamicSharedMemorySize, SMEM_TOTAL);
        attr_set = true;
    }

    int sms = 148;
    cudaDeviceGetAttribute(&sms, cudaDevAttrMultiProcessorCount, 0);
    const int G = 2 * sms;               // persistent grid: 2 CTAs per SM

    bingemm_kernel<<<G, THREADS, SMEM_TOTAL>>>(
        (const __half*)p_xa, (const __half*)p_wb, bias, out);
}

// round 16
// speedup vs baseline: 1.0340x; 1.0340x over previous
#include <cuda_runtime.h>
#include <cuda_fp16.h>
#include <cstdint>

// ============================================================================
// out[M,N] = X[M,K] @ sign(W)[N,K]^T + bias[N],  M=N=K=4096, fp32.
// sm_103 plain PTX target => legacy mma.sync fp16 path.
// History: fp16 412 (R6); 2CTA/SM 356 (R7); 4-warp 64x64 340 (R8);
// persistent 334 (R13); load-before-wait + MLP4 converts 324 (R14 BEST,
// tensor 77.2%); 8-warp retry 354 REGRESSED (R15, LDS traffic).
// R16: kill the persistent-schedule imbalance (some CTAs got 4 tiles, most 3):
// every CTA does NF=NTILES/G full tiles; the L leftover tiles are split along
// N into 2L half-tiles (128x64), one per CTA (disjoint outputs, no reduction).
// Full-tile loop byte-identical to R14; half-tile loop = verified R9 mapping.
// ============================================================================

static constexpr int MM = 4096;
static constexpr int NN = 4096;
static constexpr int KK = 4096;

static constexpr int BM = 128;
static constexpr int BN = 128;
static constexpr int BK = 64;            // 64 fp16 = 128B row
static constexpr int STAGES = 3;
static constexpr int CPT = KK / BK;      // 64 chunks per tile
static constexpr int THREADS = 128;      // 4 warps: 2 (M) x 2 (N), warp 64x64
static constexpr int NTILES = (MM / BM) * (NN / BN);  // 1024

// SMEM stage layout (bytes)
static constexpr int A_BYTES = BM * 128;           // 16384
static constexpr int B_BYTES = BN * 128;           // 16384
static constexpr int A_OFF = 0;
static constexpr int B_OFF = A_BYTES;
static constexpr int STAGE_BYTES = A_BYTES + B_BYTES;   // 32768
static constexpr int SMEM_TOTAL = STAGES * STAGE_BYTES; // 98304

// ---------------------------------------------------------------------------
// Scratch (allocation-free)
// ---------------------------------------------------------------------------
__device__ __align__(1024) __half g_xa[(size_t)MM * KK];
__device__ __align__(1024) __half g_wb[(size_t)NN * KK];

// ---------------------------------------------------------------------------
// helpers
// ---------------------------------------------------------------------------
__device__ __forceinline__ uint32_t smem_u32(const void* p) {
    uint32_t a;
    asm("{ .reg .u64 t; cvta.to.shared.u64 t, %1; cvt.u32.u64 %0, t; }"
        : "=r"(a) : "l"(p));
    return a;
}

#define CP_ASYNC_16(dst, src) \
    asm volatile("cp.async.cg.shared.global [%0], [%1], 16;" \
        :: "r"(dst), "l"(src) : "memory")
#define CP_ASYNC_COMMIT() asm volatile("cp.async.commit_group;" ::: "memory")
#define CP_ASYNC_WAIT_2() asm volatile("cp.async.wait_group 2;" ::: "memory")
#define CP_ASYNC_WAIT_0() asm volatile("cp.async.wait_group 0;" ::: "memory")

__device__ __forceinline__ void ldmatrix_x4(uint32_t& r0, uint32_t& r1,
                                            uint32_t& r2, uint32_t& r3,
                                            uint32_t addr) {
    asm volatile("ldmatrix.sync.aligned.m8n8.x4.shared.b16 {%0,%1,%2,%3}, [%4];"
                 : "=r"(r0), "=r"(r1), "=r"(r2), "=r"(r3) : "r"(addr));
}

__device__ __forceinline__ void mma_f16(float* d, const uint32_t* a,
                                        uint32_t b0, uint32_t b1) {
    asm volatile(
        "mma.sync.aligned.m16n8k16.row.col.f32.f16.f16.f32 "
        "{%0,%1,%2,%3}, {%4,%5,%6,%7}, {%8,%9}, {%0,%1,%2,%3};"
        : "+f"(d[0]), "+f"(d[1]), "+f"(d[2]), "+f"(d[3])
        : "r"(a[0]), "r"(a[1]), "r"(a[2]), "r"(a[3]), "r"(b0), "r"(b1));
}

// ---------------------------------------------------------------------------
// Fused conversion kernel, MLP=4 (unchanged from R14)
// ---------------------------------------------------------------------------
__global__ void __launch_bounds__(256) convert_fused_kernel(
    const float4* __restrict__ x, const float4* __restrict__ w,
    uint2* __restrict__ xa, uint2* __restrict__ wb, int nbx, int quarter) {
    const int b = blockIdx.x;
    if (b < nbx) {
        const int i = b * 256 + threadIdx.x;
        float4 v[4];
        #pragma unroll
        for (int k = 0; k < 4; k++) v[k] = x[i + k * quarter];
        #pragma unroll
        for (int k = 0; k < 4; k++) {
            __half2 p01 = __floats2half2_rn(v[k].x, v[k].y);
            __half2 p23 = __floats2half2_rn(v[k].z, v[k].w);
            uint2 p;
            p.x = *reinterpret_cast<uint32_t*>(&p01);
            p.y = *reinterpret_cast<uint32_t*>(&p23);
            xa[i + k * quarter] = p;
        }
    } else {
        const int i = (b - nbx) * 256 + threadIdx.x;
        float4 v[4];
        #pragma unroll
        for (int k = 0; k < 4; k++) v[k] = w[i + k * quarter];
        #pragma unroll
        for (int k = 0; k < 4; k++) {
            float s0 = (v[k].x > 0.f) ? 1.f : ((v[k].x < 0.f) ? -1.f : 0.f);
            float s1 = (v[k].y > 0.f) ? 1.f : ((v[k].y < 0.f) ? -1.f : 0.f);
            float s2 = (v[k].z > 0.f) ? 1.f : ((v[k].z < 0.f) ? -1.f : 0.f);
            float s3 = (v[k].w > 0.f) ? 1.f : ((v[k].w < 0.f) ? -1.f : 0.f);
            __half2 p01 = __floats2half2_rn(s0, s1);
            __half2 p23 = __floats2half2_rn(s2, s3);
            uint2 p;
            p.x = *reinterpret_cast<uint32_t*>(&p01);
            p.y = *reinterpret_cast<uint32_t*>(&p23);
            wb[i + k * quarter] = p;
        }
    }
}

// ---------------------------------------------------------------------------
// Persistent GEMM kernel (single fp16 pass, 4 warps, 2 CTAs/SM)
// Phase 1: NF full 128x128 tiles per CTA (R14 loop, byte-identical).
// Phase 2: one 128x64 half-tile for CTAs with blockIdx < 2L (R9 mapping).
// ---------------------------------------------------------------------------
__global__ void __launch_bounds__(THREADS, 2)
bingemm_kernel(const __half* __restrict__ xa,
               const __half* __restrict__ wb,
               const float* __restrict__ bias,
               float* __restrict__ out) {
    extern __shared__ __align__(1024) char smem[];
    const uint32_t sb = smem_u32(smem);

    const int tid = threadIdx.x;
    const int wid = tid >> 5;
    const int lane = tid & 31;
    const int warp_m = wid & 1;    // 0..1 -> 64 rows
    const int warp_n = wid >> 1;   // 0..1 -> 64 cols (full) / 32 cols (half)
    const int G = gridDim.x;

    const int NF = NTILES / G;         // full rounds per CTA (3 for G~296-341)
    const int L  = NTILES - NF * G;    // leftover tiles -> 2L half-tiles
    const int ntotal = NF * CPT;       // global chunk count, full phase

    // --- cp.async tile loader (row = 128B = 8 x 16B chunks, xor swizzle) ---
    const int ld_row = tid >> 3;   // 0..15
    const int ld_chunk = tid & 7;  // 0..7

    auto load_gchunk = [&](int stage, int gc) {
        const int tile = blockIdx.x + (gc >> 6) * G;   // gc/CPT
        const int m0 = (tile >> 5) * BM;               // tile / 32
        const int n0 = (tile & 31) * BN;               // tile % 32
        const int k0 = (gc & 63) * BK;
        const uint32_t sbase = sb + stage * STAGE_BYTES;
        #pragma unroll
        for (int i = 0; i < 8; i++) {
            int row = i * 16 + ld_row;
            uint32_t soff = row * 128 + ((ld_chunk ^ (row & 7)) << 4);
            CP_ASYNC_16(sbase + A_OFF + soff,
                        xa + (size_t)(m0 + row) * KK + k0 + ld_chunk * 8);
        }
        #pragma unroll
        for (int i = 0; i < 8; i++) {
            int row = i * 16 + ld_row;
            uint32_t soff = row * 128 + ((ld_chunk ^ (row & 7)) << 4);
            CP_ASYNC_16(sbase + B_OFF + soff,
                        wb + (size_t)(n0 + row) * KK + k0 + ld_chunk * 8);
        }
    };

    // prologue: 2 stages in flight (once per CTA)
    load_gchunk(0, 0); CP_ASYNC_COMMIT();
    load_gchunk(1, 1); CP_ASYNC_COMMIT();

    // --- ldmatrix per-thread address components ---
    const int mt = lane >> 3;            // matrix index 0..3
    const int lrow = lane & 7;
    const int a_row = warp_m * 64 + lrow + ((mt & 1) << 3);    // + mi*16
    const int a_koff = mt >> 1;
    const int b_rowF = warp_n * 64 + lrow + ((mt >> 1) << 3);  // full tile
    const int b_rowH = warp_n * 32 + lrow + ((mt >> 1) << 3);  // half tile
    const int b_koff = mt & 1;

    float acc[4][8][4];                  // mi, nj (8 x n8), quad
    #pragma unroll
    for (int mi = 0; mi < 4; mi++)
        #pragma unroll
        for (int nj = 0; nj < 8; nj++)
            #pragma unroll
            for (int q = 0; q < 4; q++) acc[mi][nj][q] = 0.f;

    const int qcol = (lane & 3) * 2;

    // ==================== Phase 1: NF full tiles ====================
    for (int ti = 0; ti < NF; ti++) {
        for (int c = 0; c < CPT; c++) {
            const int gc = ti * CPT + c;
            if (gc + 2 < ntotal) load_gchunk((gc + 2) % STAGES, gc + 2);
            CP_ASYNC_COMMIT();
            CP_ASYNC_WAIT_2();
            __syncthreads();

            const uint32_t sbase = sb + (gc % STAGES) * STAGE_BYTES;

            #pragma unroll
            for (int ks = 0; ks < 4; ks++) {
                uint32_t b[4][4];
                #pragma unroll
                for (int nj2 = 0; nj2 < 4; nj2++) {
                    int row = b_rowF + nj2 * 16;
                    int kch = ks * 2 + b_koff;
                    uint32_t off = row * 128 + ((kch ^ (row & 7)) << 4);
                    ldmatrix_x4(b[nj2][0], b[nj2][1], b[nj2][2], b[nj2][3],
                                sbase + B_OFF + off);
                }
                #pragma unroll
                for (int mi = 0; mi < 4; mi++) {
                    int row = a_row + mi * 16;
                    int kch = ks * 2 + a_koff;
                    uint32_t off = row * 128 + ((kch ^ (row & 7)) << 4);
                    uint32_t a[4];
                    ldmatrix_x4(a[0], a[1], a[2], a[3], sbase + A_OFF + off);
                    #pragma unroll
                    for (int nj2 = 0; nj2 < 4; nj2++) {
                        mma_f16(acc[mi][nj2 * 2 + 0], a, b[nj2][0], b[nj2][1]);
                        mma_f16(acc[mi][nj2 * 2 + 1], a, b[nj2][2], b[nj2][3]);
                    }
                }
            }
            __syncthreads();
        }

        // epilogue (next loads already in flight)
        {
            const int tile = blockIdx.x + ti * G;
            const int m0 = (tile >> 5) * BM;
            const int n0 = (tile & 31) * BN;

            #pragma unroll
            for (int mi = 0; mi < 4; mi++) {
                int r0 = m0 + warp_m * 64 + mi * 16 + (lane >> 2);
                float* p0 = out + (size_t)r0 * NN + n0 + warp_n * 64 + qcol;
                float* p1 = p0 + 8 * NN;
                #pragma unroll
                for (int nj = 0; nj < 8; nj++) {
                    float2 bv = *reinterpret_cast<const float2*>(
                        bias + n0 + warp_n * 64 + nj * 8 + qcol);
                    float2 v0, v1;
                    v0.x = acc[mi][nj][0] + bv.x;
                    v0.y = acc[mi][nj][1] + bv.y;
                    v1.x = acc[mi][nj][2] + bv.x;
                    v1.y = acc[mi][nj][3] + bv.y;
                    *reinterpret_cast<float2*>(p0 + nj * 8) = v0;
                    *reinterpret_cast<float2*>(p1 + nj * 8) = v1;
                    acc[mi][nj][0] = 0.f; acc[mi][nj][1] = 0.f;
                    acc[mi][nj][2] = 0.f; acc[mi][nj][3] = 0.f;
                }
            }
        }
    }

    // ==================== Phase 2: one 128x64 half-tile ====================
    const int h = blockIdx.x;
    if (h < 2 * L) {
        const int tile = NF * G + (h >> 1);
        const int nhalf = h & 1;
        const int m0 = (tile >> 5) * BM;
        const int n0 = (tile & 31) * BN + nhalf * 64;

        // drain old groups, then fresh prologue
        CP_ASYNC_WAIT_0();
        __syncthreads();

        auto load_half = [&](int stage, int c) {
            const int k0 = c * BK;
            const uint32_t sbase = sb + stage * STAGE_BYTES;
            #pragma unroll
            for (int i = 0; i < 8; i++) {
                int row = i * 16 + ld_row;
                uint32_t soff = row * 128 + ((ld_chunk ^ (row & 7)) << 4);
                CP_ASYNC_16(sbase + A_OFF + soff,
                            xa + (size_t)(m0 + row) * KK + k0 + ld_chunk * 8);
            }
            #pragma unroll
            for (int i = 0; i < 4; i++) {
                int row = i * 16 + ld_row;
                uint32_t soff = row * 128 + ((ld_chunk ^ (row & 7)) << 4);
                CP_ASYNC_16(sbase + B_OFF + soff,
                            wb + (size_t)(n0 + row) * KK + k0 + ld_chunk * 8);
            }
        };

        load_half(0, 0); CP_ASYNC_COMMIT();
        load_half(1, 1); CP_ASYNC_COMMIT();

        for (int c = 0; c < CPT; c++) {
            if (c + 2 < CPT) load_half((c + 2) % STAGES, c + 2);
            CP_ASYNC_COMMIT();
            CP_ASYNC_WAIT_2();
            __syncthreads();

            const uint32_t sbase = sb + (c % STAGES) * STAGE_BYTES;

            #pragma unroll
            for (int ks = 0; ks < 4; ks++) {
                uint32_t b[2][4];
                #pragma unroll
                for (int nj2 = 0; nj2 < 2; nj2++) {
                    int row = b_rowH + nj2 * 16;
                    int kch = ks * 2 + b_koff;
                    uint32_t off = row * 128 + ((kch ^ (row & 7)) << 4);
                    ldmatrix_x4(b[nj2][0], b[nj2][1], b[nj2][2], b[nj2][3],
                                sbase + B_OFF + off);
                }
                #pragma unroll
                for (int mi = 0; mi < 4; mi++) {
                    int row = a_row + mi * 16;
                    int kch = ks * 2 + a_koff;
                    uint32_t off = row * 128 + ((kch ^ (row & 7)) << 4);
                    uint32_t a[4];
                    ldmatrix_x4(a[0], a[1], a[2], a[3], sbase + A_OFF + off);
                    #pragma unroll
                    for (int nj2 = 0; nj2 < 2; nj2++) {
                        mma_f16(acc[mi][nj2 * 2 + 0], a, b[nj2][0], b[nj2][1]);
                        mma_f16(acc[mi][nj2 * 2 + 1], a, b[nj2][2], b[nj2][3]);
                    }
                }
            }
            __syncthreads();
        }

        // half-tile epilogue: 32 cols per warp
        #pragma unroll
        for (int mi = 0; mi < 4; mi++) {
            int r0 = m0 + warp_m * 64 + mi * 16 + (lane >> 2);
            float* p0 = out + (size_t)r0 * NN + n0 + warp_n * 32 + qcol;
            float* p1 = p0 + 8 * NN;
            #pragma unroll
            for (int nj = 0; nj < 4; nj++) {
                float2 bv = *reinterpret_cast<const float2*>(
                    bias + n0 + warp_n * 32 + nj * 8 + qcol);
                float2 v0, v1;
                v0.x = acc[mi][nj][0] + bv.x;
                v0.y = acc[mi][nj][1] + bv.y;
                v1.x = acc[mi][nj][2] + bv.x;
                v1.y = acc[mi][nj][3] + bv.y;
                *reinterpret_cast<float2*>(p0 + nj * 8) = v0;
                *reinterpret_cast<float2*>(p1 + nj * 8) = v1;
            }
        }
    }
}

// ---------------------------------------------------------------------------
// Host launch
// ---------------------------------------------------------------------------
extern "C" void kernel_launch(void* const* d_in, const int* in_sizes, int n_in,
                              void* d_out, int out_size) {
    const float* x    = (const float*)d_in[0];
    const float* w    = (const float*)d_in[1];
    const float* bias = (const float*)d_in[2];
    float* out = (float*)d_out;

    void *p_xa = nullptr, *p_wb = nullptr;
    cudaGetSymbolAddress(&p_xa, g_xa);
    cudaGetSymbolAddress(&p_wb, g_wb);

    const int n4 = MM * KK / 4;          // float4 count per tensor
    const int quarter = n4 / 4;
    const int nbx = quarter / 256;       // blocks per tensor (each does 4x)
    convert_fused_kernel<<<2 * nbx, 256>>>((const float4*)x, (const float4*)w,
                                           (uint2*)p_xa, (uint2*)p_wb,
                                           nbx, quarter);

    static bool attr_set = false;
    if (!attr_set) {
        cudaFuncSetAttribute(bingemm_kernel,
                             cudaFuncAttributeMaxDynamicSharedMemorySize, SMEM_TOTAL);
        attr_set = true;
    }

    int sms = 148;
    cudaDeviceGetAttribute(&sms, cudaDevAttrMultiProcessorCount, 0);
    const int G = 2 * sms;               // persistent grid: 2 CTAs per SM

    bingemm_kernel<<<G, THREADS, SMEM_TOTAL>>>(
        (const __half*)p_xa, (const __half*)p_wb, bias, out);
}

// round 17
// speedup vs baseline: 1.1130x; 1.0763x over previous
#include <cuda_runtime.h>
#include <cuda_fp16.h>
#include <cstdint>

// ============================================================================
// out[M,N] = X[M,K] @ sign(W)[N,K]^T + bias[N],  M=N=K=4096, fp32.
// sm_103 plain PTX target => legacy mma.sync fp16 path.
// History: fp16 412 (R6); 2CTA/SM 356 (R7); 4-warp 64x64 340 (R8);
// persistent 334 (R13); load-before-wait + MLP4 converts 324 (R14);
// 8-warp retry 354 (R15); half-tile balance 342 wall BUT ncu GEMM 312 (R16)
// -> balance fix works, the phase-2 pipeline drain leaked it.
// R17: ONE continuous chunk stream: CTAs with a half-tile process
// ntotal+64 chunks; loader dispatches full vs half addressing by index.
// The 3-stage ring rotates across the phase boundary - no drain, no
// exposed prologue. Full-tile loop byte-identical to R14.
// ============================================================================

static constexpr int MM = 4096;
static constexpr int NN = 4096;
static constexpr int KK = 4096;

static constexpr int BM = 128;
static constexpr int BN = 128;
static constexpr int BK = 64;            // 64 fp16 = 128B row
static constexpr int STAGES = 3;
static constexpr int CPT = KK / BK;      // 64 chunks per tile
static constexpr int THREADS = 128;      // 4 warps: 2 (M) x 2 (N), warp 64x64
static constexpr int NTILES = (MM / BM) * (NN / BN);  // 1024

// SMEM stage layout (bytes)
static constexpr int A_BYTES = BM * 128;           // 16384
static constexpr int B_BYTES = BN * 128;           // 16384
static constexpr int A_OFF = 0;
static constexpr int B_OFF = A_BYTES;
static constexpr int STAGE_BYTES = A_BYTES + B_BYTES;   // 32768
static constexpr int SMEM_TOTAL = STAGES * STAGE_BYTES; // 98304

// ---------------------------------------------------------------------------
// Scratch (allocation-free)
// ---------------------------------------------------------------------------
__device__ __align__(1024) __half g_xa[(size_t)MM * KK];
__device__ __align__(1024) __half g_wb[(size_t)NN * KK];

// ---------------------------------------------------------------------------
// helpers
// ---------------------------------------------------------------------------
__device__ __forceinline__ uint32_t smem_u32(const void* p) {
    uint32_t a;
    asm("{ .reg .u64 t; cvta.to.shared.u64 t, %1; cvt.u32.u64 %0, t; }"
        : "=r"(a) : "l"(p));
    return a;
}

#define CP_ASYNC_16(dst, src) \
    asm volatile("cp.async.cg.shared.global [%0], [%1], 16;" \
        :: "r"(dst), "l"(src) : "memory")
#define CP_ASYNC_COMMIT() asm volatile("cp.async.commit_group;" ::: "memory")
#define CP_ASYNC_WAIT_2() asm volatile("cp.async.wait_group 2;" ::: "memory")

__device__ __forceinline__ void ldmatrix_x4(uint32_t& r0, uint32_t& r1,
                                            uint32_t& r2, uint32_t& r3,
                                            uint32_t addr) {
    asm volatile("ldmatrix.sync.aligned.m8n8.x4.shared.b16 {%0,%1,%2,%3}, [%4];"
                 : "=r"(r0), "=r"(r1), "=r"(r2), "=r"(r3) : "r"(addr));
}

__device__ __forceinline__ void mma_f16(float* d, const uint32_t* a,
                                        uint32_t b0, uint32_t b1) {
    asm volatile(
        "mma.sync.aligned.m16n8k16.row.col.f32.f16.f16.f32 "
        "{%0,%1,%2,%3}, {%4,%5,%6,%7}, {%8,%9}, {%0,%1,%2,%3};"
        : "+f"(d[0]), "+f"(d[1]), "+f"(d[2]), "+f"(d[3])
        : "r"(a[0]), "r"(a[1]), "r"(a[2]), "r"(a[3]), "r"(b0), "r"(b1));
}

// ---------------------------------------------------------------------------
// Fused conversion kernel, MLP=4 (unchanged from R14)
// ---------------------------------------------------------------------------
__global__ void __launch_bounds__(256) convert_fused_kernel(
    const float4* __restrict__ x, const float4* __restrict__ w,
    uint2* __restrict__ xa, uint2* __restrict__ wb, int nbx, int quarter) {
    const int b = blockIdx.x;
    if (b < nbx) {
        const int i = b * 256 + threadIdx.x;
        float4 v[4];
        #pragma unroll
        for (int k = 0; k < 4; k++) v[k] = x[i + k * quarter];
        #pragma unroll
        for (int k = 0; k < 4; k++) {
            __half2 p01 = __floats2half2_rn(v[k].x, v[k].y);
            __half2 p23 = __floats2half2_rn(v[k].z, v[k].w);
            uint2 p;
            p.x = *reinterpret_cast<uint32_t*>(&p01);
            p.y = *reinterpret_cast<uint32_t*>(&p23);
            xa[i + k * quarter] = p;
        }
    } else {
        const int i = (b - nbx) * 256 + threadIdx.x;
        float4 v[4];
        #pragma unroll
        for (int k = 0; k < 4; k++) v[k] = w[i + k * quarter];
        #pragma unroll
        for (int k = 0; k < 4; k++) {
            float s0 = (v[k].x > 0.f) ? 1.f : ((v[k].x < 0.f) ? -1.f : 0.f);
            float s1 = (v[k].y > 0.f) ? 1.f : ((v[k].y < 0.f) ? -1.f : 0.f);
            float s2 = (v[k].z > 0.f) ? 1.f : ((v[k].z < 0.f) ? -1.f : 0.f);
            float s3 = (v[k].w > 0.f) ? 1.f : ((v[k].w < 0.f) ? -1.f : 0.f);
            __half2 p01 = __floats2half2_rn(s0, s1);
            __half2 p23 = __floats2half2_rn(s2, s3);
            uint2 p;
            p.x = *reinterpret_cast<uint32_t*>(&p01);
            p.y = *reinterpret_cast<uint32_t*>(&p23);
            wb[i + k * quarter] = p;
        }
    }
}

// ---------------------------------------------------------------------------
// Persistent GEMM kernel (single fp16 pass, 4 warps, 2 CTAs/SM)
// Unified chunk stream: [0, ntotal) full tiles, [ntotal, ntotal+64) half tile.
// ---------------------------------------------------------------------------
__global__ void __launch_bounds__(THREADS, 2)
bingemm_kernel(const __half* __restrict__ xa,
               const __half* __restrict__ wb,
               const float* __restrict__ bias,
               float* __restrict__ out) {
    extern __shared__ __align__(1024) char smem[];
    const uint32_t sb = smem_u32(smem);

    const int tid = threadIdx.x;
    const int wid = tid >> 5;
    const int lane = tid & 31;
    const int warp_m = wid & 1;    // 0..1 -> 64 rows
    const int warp_n = wid >> 1;   // 0..1 -> 64 cols (full) / 32 cols (half)
    const int G = gridDim.x;

    const int NF = NTILES / G;         // full rounds per CTA
    const int L  = NTILES - NF * G;    // leftover tiles -> 2L half-tiles
    const int ntotal = NF * CPT;       // full-phase chunk count

    const int h = blockIdx.x;
    const bool has_half = (h < 2 * L);
    int m0h = 0, n0h = 0;
    if (has_half) {
        const int tile = NF * G + (h >> 1);
        m0h = (tile >> 5) * BM;
        n0h = (tile & 31) * BN + (h & 1) * 64;
    }
    const int ngrand = ntotal + (has_half ? CPT : 0);

    // --- cp.async loader (row = 128B = 8 x 16B chunks, xor swizzle) ---
    const int ld_row = tid >> 3;   // 0..15
    const int ld_chunk = tid & 7;  // 0..7

    auto load_any = [&](int stage, int gc) {
        const uint32_t sbase = sb + stage * STAGE_BYTES;
        if (gc < ntotal) {
            const int tile = blockIdx.x + (gc >> 6) * G;   // gc/CPT
            const int m0 = (tile >> 5) * BM;
            const int n0 = (tile & 31) * BN;
            const int k0 = (gc & 63) * BK;
            #pragma unroll
            for (int i = 0; i < 8; i++) {
                int row = i * 16 + ld_row;
                uint32_t soff = row * 128 + ((ld_chunk ^ (row & 7)) << 4);
                CP_ASYNC_16(sbase + A_OFF + soff,
                            xa + (size_t)(m0 + row) * KK + k0 + ld_chunk * 8);
            }
            #pragma unroll
            for (int i = 0; i < 8; i++) {
                int row = i * 16 + ld_row;
                uint32_t soff = row * 128 + ((ld_chunk ^ (row & 7)) << 4);
                CP_ASYNC_16(sbase + B_OFF + soff,
                            wb + (size_t)(n0 + row) * KK + k0 + ld_chunk * 8);
            }
        } else {
            const int k0 = (gc - ntotal) * BK;
            #pragma unroll
            for (int i = 0; i < 8; i++) {
                int row = i * 16 + ld_row;
                uint32_t soff = row * 128 + ((ld_chunk ^ (row & 7)) << 4);
                CP_ASYNC_16(sbase + A_OFF + soff,
                            xa + (size_t)(m0h + row) * KK + k0 + ld_chunk * 8);
            }
            #pragma unroll
            for (int i = 0; i < 4; i++) {
                int row = i * 16 + ld_row;
                uint32_t soff = row * 128 + ((ld_chunk ^ (row & 7)) << 4);
                CP_ASYNC_16(sbase + B_OFF + soff,
                            wb + (size_t)(n0h + row) * KK + k0 + ld_chunk * 8);
            }
        }
    };

    // prologue: 2 stages in flight (once per CTA)
    load_any(0, 0); CP_ASYNC_COMMIT();
    load_any(1, 1); CP_ASYNC_COMMIT();

    // --- ldmatrix per-thread address components ---
    const int mt = lane >> 3;            // matrix index 0..3
    const int lrow = lane & 7;
    const int a_row = warp_m * 64 + lrow + ((mt & 1) << 3);    // + mi*16
    const int a_koff = mt >> 1;
    const int b_rowF = warp_n * 64 + lrow + ((mt >> 1) << 3);  // full tile
    const int b_rowH = warp_n * 32 + lrow + ((mt >> 1) << 3);  // half tile
    const int b_koff = mt & 1;

    float acc[4][8][4];                  // mi, nj (8 x n8), quad
    #pragma unroll
    for (int mi = 0; mi < 4; mi++)
        #pragma unroll
        for (int nj = 0; nj < 8; nj++)
            #pragma unroll
            for (int q = 0; q < 4; q++) acc[mi][nj][q] = 0.f;

    const int qcol = (lane & 3) * 2;

    // ==================== Phase 1: NF full tiles ====================
    for (int ti = 0; ti < NF; ti++) {
        for (int c = 0; c < CPT; c++) {
            const int gc = ti * CPT + c;
            if (gc + 2 < ngrand) load_any((gc + 2) % STAGES, gc + 2);
            CP_ASYNC_COMMIT();
            CP_ASYNC_WAIT_2();
            __syncthreads();

            const uint32_t sbase = sb + (gc % STAGES) * STAGE_BYTES;

            #pragma unroll
            for (int ks = 0; ks < 4; ks++) {
                uint32_t b[4][4];
                #pragma unroll
                for (int nj2 = 0; nj2 < 4; nj2++) {
                    int row = b_rowF + nj2 * 16;
                    int kch = ks * 2 + b_koff;
                    uint32_t off = row * 128 + ((kch ^ (row & 7)) << 4);
                    ldmatrix_x4(b[nj2][0], b[nj2][1], b[nj2][2], b[nj2][3],
                                sbase + B_OFF + off);
                }
                #pragma unroll
                for (int mi = 0; mi < 4; mi++) {
                    int row = a_row + mi * 16;
                    int kch = ks * 2 + a_koff;
                    uint32_t off = row * 128 + ((kch ^ (row & 7)) << 4);
                    uint32_t a[4];
                    ldmatrix_x4(a[0], a[1], a[2], a[3], sbase + A_OFF + off);
                    #pragma unroll
                    for (int nj2 = 0; nj2 < 4; nj2++) {
                        mma_f16(acc[mi][nj2 * 2 + 0], a, b[nj2][0], b[nj2][1]);
                        mma_f16(acc[mi][nj2 * 2 + 1], a, b[nj2][2], b[nj2][3]);
                    }
                }
            }
            __syncthreads();
        }

        // epilogue (subsequent chunk loads already in flight)
        {
            const int tile = blockIdx.x + ti * G;
            const int m0 = (tile >> 5) * BM;
            const int n0 = (tile & 31) * BN;

            #pragma unroll
            for (int mi = 0; mi < 4; mi++) {
                int r0 = m0 + warp_m * 64 + mi * 16 + (lane >> 2);
                float* p0 = out + (size_t)r0 * NN + n0 + warp_n * 64 + qcol;
                float* p1 = p0 + 8 * NN;
                #pragma unroll
                for (int nj = 0; nj < 8; nj++) {
                    float2 bv = *reinterpret_cast<const float2*>(
                        bias + n0 + warp_n * 64 + nj * 8 + qcol);
                    float2 v0, v1;
                    v0.x = acc[mi][nj][0] + bv.x;
                    v0.y = acc[mi][nj][1] + bv.y;
                    v1.x = acc[mi][nj][2] + bv.x;
                    v1.y = acc[mi][nj][3] + bv.y;
                    *reinterpret_cast<float2*>(p0 + nj * 8) = v0;
                    *reinterpret_cast<float2*>(p1 + nj * 8) = v1;
                    acc[mi][nj][0] = 0.f; acc[mi][nj][1] = 0.f;
                    acc[mi][nj][2] = 0.f; acc[mi][nj][3] = 0.f;
                }
            }
        }
    }

    // ==================== Phase 2: one 128x64 half-tile ====================
    if (has_half) {
        for (int c = 0; c < CPT; c++) {
            const int gc = ntotal + c;
            if (gc + 2 < ngrand) load_any((gc + 2) % STAGES, gc + 2);
            CP_ASYNC_COMMIT();
            CP_ASYNC_WAIT_2();
            __syncthreads();

            const uint32_t sbase = sb + (gc % STAGES) * STAGE_BYTES;

            #pragma unroll
            for (int ks = 0; ks < 4; ks++) {
                uint32_t b[2][4];
                #pragma unroll
                for (int nj2 = 0; nj2 < 2; nj2++) {
                    int row = b_rowH + nj2 * 16;
                    int kch = ks * 2 + b_koff;
                    uint32_t off = row * 128 + ((kch ^ (row & 7)) << 4);
                    ldmatrix_x4(b[nj2][0], b[nj2][1], b[nj2][2], b[nj2][3],
                                sbase + B_OFF + off);
                }
                #pragma unroll
                for (int mi = 0; mi < 4; mi++) {
                    int row = a_row + mi * 16;
                    int kch = ks * 2 + a_koff;
                    uint32_t off = row * 128 + ((kch ^ (row & 7)) << 4);
                    uint32_t a[4];
                    ldmatrix_x4(a[0], a[1], a[2], a[3], sbase + A_OFF + off);
                    #pragma unroll
                    for (int nj2 = 0; nj2 < 2; nj2++) {
                        mma_f16(acc[mi][nj2 * 2 + 0], a, b[nj2][0], b[nj2][1]);
                        mma_f16(acc[mi][nj2 * 2 + 1], a, b[nj2][2], b[nj2][3]);
                    }
                }
            }
            __syncthreads();
        }

        // half-tile epilogue: 32 cols per warp
        #pragma unroll
        for (int mi = 0; mi < 4; mi++) {
            int r0 = m0h + warp_m * 64 + mi * 16 + (lane >> 2);
            float* p0 = out + (size_t)r0 * NN + n0h + warp_n * 32 + qcol;
            float* p1 = p0 + 8 * NN;
            #pragma unroll
            for (int nj = 0; nj < 4; nj++) {
                float2 bv = *reinterpret_cast<const float2*>(
                    bias + n0h + warp_n * 32 + nj * 8 + qcol);
                float2 v0, v1;
                v0.x = acc[mi][nj][0] + bv.x;
                v0.y = acc[mi][nj][1] + bv.y;
                v1.x = acc[mi][nj][2] + bv.x;
                v1.y = acc[mi][nj][3] + bv.y;
                *reinterpret_cast<float2*>(p0 + nj * 8) = v0;
                *reinterpret_cast<float2*>(p1 + nj * 8) = v1;
            }
        }
    }
}

// ---------------------------------------------------------------------------
// Host launch
// ---------------------------------------------------------------------------
extern "C" void kernel_launch(void* const* d_in, const int* in_sizes, int n_in,
                              void* d_out, int out_size) {
    const float* x    = (const float*)d_in[0];
    const float* w    = (const float*)d_in[1];
    const float* bias = (const float*)d_in[2];
    float* out = (float*)d_out;

    void *p_xa = nullptr, *p_wb = nullptr;
    cudaGetSymbolAddress(&p_xa, g_xa);
    cudaGetSymbolAddress(&p_wb, g_wb);

    const int n4 = MM * KK / 4;          // float4 count per tensor
    const int quarter = n4 / 4;
    const int nbx = quarter / 256;       // blocks per tensor (each does 4x)
    convert_fused_kernel<<<2 * nbx, 256>>>((const float4*)x, (const float4*)w,
                                           (uint2*)p_xa, (uint2*)p_wb,
                                           nbx, quarter);

    static bool attr_set = false;
    if (!attr_set) {
        cudaFuncSetAttribute(bingemm_kernel,
                             cudaFuncAttributeMaxDynamicSharedMemorySize, SMEM_TOTAL);
        attr_set = true;
    }

    int sms = 148;
    cudaDeviceGetAttribute(&sms, cudaDevAttrMultiProcessorCount, 0);
    const int G = 2 * sms;               // persistent grid: 2 CTAs per SM

    bingemm_kernel<<<G, THREADS, SMEM_TOTAL>>>(
        (const __half*)p_xa, (const __half*)p_wb, bias, out);
}